// round 1
// baseline (speedup 1.0000x reference)
#include <cuda_runtime.h>
#include <math.h>

// ---------------- problem constants (fixed by setup_inputs) ----------------
#define BB   8
#define LQ   3072
#define CC   768
#define LIN  4096          // 64*64 feature tokens
#define HL   64
#define WL   64
#define NH   6
#define NP   4
#define HID  192
#define HH   32
#define WW   32
#define MQ   (BB*LQ)       // 24576
#define MF   (BB*LIN)      // 32768

// ---------------- scratch (device globals; no allocs allowed) --------------
__device__ float g_qln [MQ*CC];
__device__ float g_fln [MF*CC];
__device__ float g_val [MF*CC];
__device__ float g_offs[MQ*(NH*NP*2)];
__device__ float g_awl [MQ*(NH*NP)];
__device__ float g_attn[MQ*CC];
__device__ float g_q2  [MQ*CC];
__device__ float g_x1  [MQ*HID];
__device__ float g_x2  [MQ*HID];

// ---------------- LayerNorm: one block per row of 768 ----------------------
__global__ void ln_kernel(const float* __restrict__ x, const float* __restrict__ w,
                          const float* __restrict__ b, float* __restrict__ y) {
    int row = blockIdx.x;
    const float* xr = x + (size_t)row * CC;
    float* yr = y + (size_t)row * CC;
    int t = threadIdx.x;                 // 256 threads, 3 elems each
    float v0 = xr[t], v1 = xr[t + 256], v2 = xr[t + 512];
    float s  = v0 + v1 + v2;
    float ss = v0*v0 + v1*v1 + v2*v2;
    __shared__ float red0[32], red1[32];
    #pragma unroll
    for (int o = 16; o; o >>= 1) {
        s  += __shfl_down_sync(0xffffffffu, s,  o);
        ss += __shfl_down_sync(0xffffffffu, ss, o);
    }
    int wid = t >> 5, lid = t & 31;
    if (lid == 0) { red0[wid] = s; red1[wid] = ss; }
    __syncthreads();
    if (wid == 0) {
        s  = (lid < 8) ? red0[lid] : 0.f;
        ss = (lid < 8) ? red1[lid] : 0.f;
        #pragma unroll
        for (int o = 4; o; o >>= 1) {
            s  += __shfl_down_sync(0xffffffffu, s,  o);
            ss += __shfl_down_sync(0xffffffffu, ss, o);
        }
        if (lid == 0) { red0[0] = s; red1[0] = ss; }
    }
    __syncthreads();
    float mean = red0[0] * (1.f / CC);
    float var  = red1[0] * (1.f / CC) - mean * mean;
    float inv  = rsqrtf(var + 1e-6f);
    yr[t]       = (v0 - mean) * inv * w[t]       + b[t];
    yr[t + 256] = (v1 - mean) * inv * w[t + 256] + b[t + 256];
    yr[t + 512] = (v2 - mean) * inv * w[t + 512] + b[t + 512];
}

// ---------------- generic tiled fp32 GEMM: C = A*W + bias (+R) -------------
// 64x64 block, BK=16, 256 threads, 4x4 per thread.
__global__ void gemm_kernel(const float* __restrict__ A, const float* __restrict__ W,
                            const float* __restrict__ bias, const float* __restrict__ R,
                            float* __restrict__ C, int M, int N, int K) {
    const int BM = 64, BN = 64, BK = 16;
    __shared__ float As[BK][BM + 1];
    __shared__ float Bs[BK][BN + 1];
    int t  = threadIdx.x;
    int m0 = blockIdx.y * BM, n0 = blockIdx.x * BN;
    int ty = t >> 4, tx = t & 15;
    float acc[4][4] = {};
    for (int k0 = 0; k0 < K; k0 += BK) {
        #pragma unroll
        for (int i = t; i < BM * BK; i += 256) {
            int r = i >> 4, kk = i & 15;
            int m = m0 + r;
            As[kk][r] = (m < M) ? A[(size_t)m * K + k0 + kk] : 0.f;
        }
        #pragma unroll
        for (int i = t; i < BK * BN; i += 256) {
            int kk = i >> 6, n = i & 63;
            Bs[kk][n] = (n0 + n < N) ? W[(size_t)(k0 + kk) * N + n0 + n] : 0.f;
        }
        __syncthreads();
        #pragma unroll
        for (int kk = 0; kk < BK; kk++) {
            float a[4], bb[4];
            #pragma unroll
            for (int i = 0; i < 4; i++) a[i]  = As[kk][ty * 4 + i];
            #pragma unroll
            for (int j = 0; j < 4; j++) bb[j] = Bs[kk][tx * 4 + j];
            #pragma unroll
            for (int i = 0; i < 4; i++)
                #pragma unroll
                for (int j = 0; j < 4; j++)
                    acc[i][j] += a[i] * bb[j];
        }
        __syncthreads();
    }
    #pragma unroll
    for (int i = 0; i < 4; i++) {
        int m = m0 + ty * 4 + i;
        if (m >= M) continue;
        #pragma unroll
        for (int j = 0; j < 4; j++) {
            int n = n0 + tx * 4 + j;
            if (n >= N) continue;
            float v = acc[i][j] + bias[n];
            if (R) v += R[(size_t)m * N + n];
            C[(size_t)m * N + n] = v;
        }
    }
}

// ------- softmax(attn weights) + bilinear sample + weighted reduce ---------
// One block per query (b,lq); 256 threads over 768 channels.
__global__ void sample_kernel(const float* __restrict__ refp, float* __restrict__ attn) {
    int q = blockIdx.x;           // b*LQ + lq
    int b = q / LQ;
    __shared__ float cw[NH][NP][4];
    __shared__ int   ci[NH][NP][4];
    __shared__ float lg[NH * NP];
    int t = threadIdx.x;
    if (t < NH * NP) lg[t] = g_awl[(size_t)q * (NH * NP) + t];
    __syncthreads();
    if (t < NH * NP) {
        int h = t >> 2;
        float l0 = lg[h*4+0], l1 = lg[h*4+1], l2 = lg[h*4+2], l3 = lg[h*4+3];
        float m  = fmaxf(fmaxf(l0, l1), fmaxf(l2, l3));
        float e0 = __expf(l0-m), e1 = __expf(l1-m), e2 = __expf(l2-m), e3 = __expf(l3-m);
        float aw = __expf(lg[t]-m) / (e0 + e1 + e2 + e3);
        float rx = refp[(size_t)q * 2 + 0];
        float ry = refp[(size_t)q * 2 + 1];
        float ox = g_offs[(size_t)q * (NH*NP*2) + t*2 + 0];
        float oy = g_offs[(size_t)q * (NH*NP*2) + t*2 + 1];
        float x = (rx + ox * (1.f / WL)) * WL - 0.5f;
        float y = (ry + oy * (1.f / HL)) * HL - 0.5f;
        float x0f = floorf(x), y0f = floorf(y);
        float wx = x - x0f, wy = y - y0f;
        int x0 = (int)x0f, y0 = (int)y0f;
        float ws[4] = {(1.f-wy)*(1.f-wx), (1.f-wy)*wx, wy*(1.f-wx), wy*wx};
        const int dys[4] = {0,0,1,1}, dxs[4] = {0,1,0,1};
        int h2 = t >> 2, p = t & 3;
        #pragma unroll
        for (int c2 = 0; c2 < 4; c2++) {
            int xi = x0 + dxs[c2], yi = y0 + dys[c2];
            bool valid = (xi >= 0) && (xi < WL) && (yi >= 0) && (yi < HL);
            ci[h2][p][c2] = valid ? (yi * WL + xi) : -1;
            cw[h2][p][c2] = valid ? ws[c2] * aw : 0.f;
        }
    }
    __syncthreads();
    const float* vb = g_val + (size_t)b * LIN * CC;
    for (int c = t; c < CC; c += 256) {
        int h = c >> 7;
        float acc = 0.f;
        #pragma unroll
        for (int p = 0; p < NP; p++)
            #pragma unroll
            for (int c2 = 0; c2 < 4; c2++) {
                int idx = ci[h][p][c2];
                if (idx >= 0) acc += vb[(size_t)idx * CC + c] * cw[h][p][c2];
            }
        attn[(size_t)q * CC + c] = acc;
    }
}

// ---------- depthwise 3x3 conv (SAME, zero pad) + bias + exact GELU --------
// One block per output pixel (b,chunk,py,px); 192 threads = channels.
__global__ void dwconv_gelu_kernel(const float* __restrict__ x, const float* __restrict__ w,
                                   const float* __restrict__ bias, float* __restrict__ y) {
    int pg = blockIdx.x;                 // 0 .. B*LQ-1
    int c  = threadIdx.x;                // 0 .. 191
    int b    = pg / LQ;
    int rem  = pg % LQ;
    int chunk = rem / (HH * WW);
    int pix   = rem % (HH * WW);
    int py = pix >> 5, px = pix & 31;
    const float* xb = x + ((size_t)b * LQ + (size_t)chunk * HH * WW) * HID;
    float acc = bias[c];
    #pragma unroll
    for (int dy = -1; dy <= 1; dy++) {
        int yy = py + dy;
        if (yy < 0 || yy >= HH) continue;
        #pragma unroll
        for (int dx = -1; dx <= 1; dx++) {
            int xx = px + dx;
            if (xx < 0 || xx >= WW) continue;
            acc += xb[(size_t)(yy * WW + xx) * HID + c] * w[c * 9 + (dy + 1) * 3 + (dx + 1)];
        }
    }
    y[(size_t)pg * HID + c] = 0.5f * acc * (1.f + erff(acc * 0.70710678118654752f));
}

// ---------------------------------------------------------------------------
extern "C" void kernel_launch(void* const* d_in, const int* in_sizes, int n_in,
                              void* d_out, int out_size) {
    const float* query = (const float*)d_in[0];
    const float* refp  = (const float*)d_in[1];
    const float* feat  = (const float*)d_in[2];
    // d_in[3]=spatial_shapes, d_in[4]=level_start_index, d_in[5]=H, d_in[6]=W (fixed)
    const float* qn_w = (const float*)d_in[7];
    const float* qn_b = (const float*)d_in[8];
    const float* fn_w = (const float*)d_in[9];
    const float* fn_b = (const float*)d_in[10];
    const float* so_w = (const float*)d_in[11];
    const float* so_b = (const float*)d_in[12];
    const float* aw_w = (const float*)d_in[13];
    const float* aw_b = (const float*)d_in[14];
    const float* vp_w = (const float*)d_in[15];
    const float* vp_b = (const float*)d_in[16];
    const float* op_w = (const float*)d_in[17];
    const float* op_b = (const float*)d_in[18];
    const float* ffn_w = (const float*)d_in[19];
    const float* ffn_b = (const float*)d_in[20];
    const float* fc1_w = (const float*)d_in[21];
    const float* fc1_b = (const float*)d_in[22];
    const float* dw_w  = (const float*)d_in[23];
    const float* dw_b  = (const float*)d_in[24];
    const float* fc2_w = (const float*)d_in[25];
    const float* fc2_b = (const float*)d_in[26];
    float* out = (float*)d_out;

    float *p_qln, *p_fln, *p_val, *p_offs, *p_awl, *p_attn, *p_q2, *p_x1, *p_x2;
    cudaGetSymbolAddress((void**)&p_qln,  g_qln);
    cudaGetSymbolAddress((void**)&p_fln,  g_fln);
    cudaGetSymbolAddress((void**)&p_val,  g_val);
    cudaGetSymbolAddress((void**)&p_offs, g_offs);
    cudaGetSymbolAddress((void**)&p_awl,  g_awl);
    cudaGetSymbolAddress((void**)&p_attn, g_attn);
    cudaGetSymbolAddress((void**)&p_q2,   g_q2);
    cudaGetSymbolAddress((void**)&p_x1,   g_x1);
    cudaGetSymbolAddress((void**)&p_x2,   g_x2);

    // 1. LayerNorms of query and feat
    ln_kernel<<<MQ, 256>>>(query, qn_w, qn_b, p_qln);
    ln_kernel<<<MF, 256>>>(feat,  fn_w, fn_b, p_fln);

    // 2. value = f_ln @ vp_w + vp_b        (32768 x 768 x 768)
    gemm_kernel<<<dim3(CC/64, MF/64), 256>>>(p_fln, vp_w, vp_b, nullptr, p_val, MF, CC, CC);

    // 3. sampling offsets & attn-weight logits
    gemm_kernel<<<dim3(1, MQ/64), 256>>>(p_qln, so_w, so_b, nullptr, p_offs, MQ, NH*NP*2, CC);
    gemm_kernel<<<dim3(1, MQ/64), 256>>>(p_qln, aw_w, aw_b, nullptr, p_awl,  MQ, NH*NP,   CC);

    // 4. softmax + bilinear sample + head-reduce
    sample_kernel<<<MQ, 256>>>(refp, p_attn);

    // 5. output projection + residual -> q2
    gemm_kernel<<<dim3(CC/64, MQ/64), 256>>>(p_attn, op_w, op_b, query, p_q2, MQ, CC, CC);

    // 6. ConvFFN: LN(q2) -> fc1 -> dwconv+gelu -> fc2 + residual
    ln_kernel<<<MQ, 256>>>(p_q2, ffn_w, ffn_b, p_qln);
    gemm_kernel<<<dim3(HID/64, MQ/64), 256>>>(p_qln, fc1_w, fc1_b, nullptr, p_x1, MQ, HID, CC);
    dwconv_gelu_kernel<<<MQ, HID>>>(p_x1, dw_w, dw_b, p_x2);
    gemm_kernel<<<dim3(CC/64, MQ/64), 256>>>(p_x2, fc2_w, fc2_b, p_q2, out, MQ, CC, HID);
}

// round 2
// speedup vs baseline: 4.0491x; 4.0491x over previous
#include <cuda_runtime.h>
#include <math.h>
#include <stdint.h>

// ---------------- problem constants (fixed by setup_inputs) ----------------
#define BB   8
#define LQ   3072
#define CC   768
#define LIN  4096          // 64*64 feature tokens
#define HL   64
#define WL   64
#define NH   6
#define NP   4
#define HID  192
#define HH   32
#define WW   32
#define MQ   (BB*LQ)       // 24576
#define MF   (BB*LIN)      // 32768
#define NOA  72            // 48 offs + 24 attn logits, fused

// ---------------- scratch (device globals; no allocs allowed) --------------
__device__ float g_qln [MQ*CC];
__device__ float g_fln [MF*CC];
__device__ float g_val [MF*CC];
__device__ float g_oa  [MQ*NOA];
__device__ float g_attn[MQ*CC];
__device__ float g_q2  [MQ*CC];
__device__ float g_x1  [MQ*HID];
__device__ float g_x2  [MQ*HID];
__device__ float g_w72 [CC*NOA];
__device__ float g_b72 [NOA];

// ---------------- helpers --------------------------------------------------
__device__ __forceinline__ uint32_t f2tf32(float x) {
    uint32_t r;
    asm("cvt.rna.tf32.f32 %0, %1;" : "=r"(r) : "f"(x));
    return r;
}
__device__ __forceinline__ void mma_tf32(float* d, const uint32_t* a, const uint32_t* b) {
    asm volatile(
        "mma.sync.aligned.m16n8k8.row.col.f32.tf32.tf32.f32 "
        "{%0,%1,%2,%3}, {%4,%5,%6,%7}, {%8,%9}, {%0,%1,%2,%3};\n"
        : "+f"(d[0]), "+f"(d[1]), "+f"(d[2]), "+f"(d[3])
        : "r"(a[0]), "r"(a[1]), "r"(a[2]), "r"(a[3]), "r"(b[0]), "r"(b[1]));
}

// ---------------- tf32 tensor-core GEMM: C = A*W + bias (+R) ---------------
// BM=128, BN=128, BK=16, 256 threads, 8 warps as 2(m) x 4(n), warp tile 64x32.
// Requires: M % 128 == 0, K % 16 == 0, N % 4 == 0 (guards on N).
#define ASTRIDE 20    // 16 + 4 pad  -> conflict-free A-fragment LDS
#define BSTRIDE 136   // 128 + 8 pad -> conflict-free B-fragment LDS
__global__ __launch_bounds__(256)
void gemm_tf32_kernel(const float* __restrict__ A, const float* __restrict__ W,
                      const float* __restrict__ bias, const float* __restrict__ R,
                      float* __restrict__ C, int M, int N, int K) {
    __shared__ uint32_t As[2][128 * ASTRIDE];
    __shared__ uint32_t Bs[2][16 * BSTRIDE];

    const int t    = threadIdx.x;
    const int lane = t & 31;
    const int g    = lane >> 2;      // groupID 0..7
    const int tg   = lane & 3;       // thread-in-group 0..3
    const int wid  = t >> 5;
    const int wm   = wid & 1;        // 0..1  -> m offset wm*64
    const int wn   = wid >> 1;       // 0..3  -> n offset wn*32

    const int m0 = blockIdx.y * 128;
    const int n0 = blockIdx.x * 128;

    // global staging coordinates
    const int ar  = t >> 2;          // A rows ar, ar+64
    const int ac  = (t & 3) * 4;     // A col offset within BK (float4)
    const int bk  = t >> 5;          // B k-rows bk, bk+8
    const int bc  = (t & 31) * 4;    // B col offset within BN (float4)
    const int nb  = n0 + bc;
    const bool bvalid = (nb < N);    // N % 4 == 0 -> whole float4 valid or not

    float acc[4][4][4] = {};
    float4 av0, av1, bv0, bv1;
    const float4 zero4 = make_float4(0.f, 0.f, 0.f, 0.f);

    // --- prologue: load k-chunk 0 ---
    {
        const float* Ap = A + (size_t)(m0 + ar) * K + ac;
        av0 = *(const float4*)Ap;
        av1 = *(const float4*)(Ap + (size_t)64 * K);
        if (bvalid) {
            const float* Bp = W + (size_t)bk * N + nb;
            bv0 = *(const float4*)Bp;
            bv1 = *(const float4*)(Bp + (size_t)8 * N);
        } else { bv0 = zero4; bv1 = zero4; }
    }
    // store chunk 0 into buffer 0
    {
        uint4 p;
        p = make_uint4(f2tf32(av0.x), f2tf32(av0.y), f2tf32(av0.z), f2tf32(av0.w));
        *(uint4*)&As[0][ar * ASTRIDE + ac] = p;
        p = make_uint4(f2tf32(av1.x), f2tf32(av1.y), f2tf32(av1.z), f2tf32(av1.w));
        *(uint4*)&As[0][(ar + 64) * ASTRIDE + ac] = p;
        p = make_uint4(f2tf32(bv0.x), f2tf32(bv0.y), f2tf32(bv0.z), f2tf32(bv0.w));
        *(uint4*)&Bs[0][bk * BSTRIDE + bc] = p;
        p = make_uint4(f2tf32(bv1.x), f2tf32(bv1.y), f2tf32(bv1.z), f2tf32(bv1.w));
        *(uint4*)&Bs[0][(bk + 8) * BSTRIDE + bc] = p;
    }
    __syncthreads();

    const int KT = K >> 4;
    int cur = 0;
    for (int it = 0; it < KT; ++it) {
        const bool more = (it + 1 < KT);
        if (more) {
            const int k0 = (it + 1) << 4;
            const float* Ap = A + (size_t)(m0 + ar) * K + k0 + ac;
            av0 = *(const float4*)Ap;
            av1 = *(const float4*)(Ap + (size_t)64 * K);
            if (bvalid) {
                const float* Bp = W + (size_t)(k0 + bk) * N + nb;
                bv0 = *(const float4*)Bp;
                bv1 = *(const float4*)(Bp + (size_t)8 * N);
            } else { bv0 = zero4; bv1 = zero4; }
        }
        // --- compute on buffer `cur` ---
        #pragma unroll
        for (int ks = 0; ks < 2; ++ks) {
            const int kb = ks * 8;
            uint32_t af[4][4], bf[4][2];
            #pragma unroll
            for (int mt = 0; mt < 4; ++mt) {
                const int r = wm * 64 + mt * 16 + g;
                af[mt][0] = As[cur][r * ASTRIDE + kb + tg];
                af[mt][1] = As[cur][(r + 8) * ASTRIDE + kb + tg];
                af[mt][2] = As[cur][r * ASTRIDE + kb + tg + 4];
                af[mt][3] = As[cur][(r + 8) * ASTRIDE + kb + tg + 4];
            }
            #pragma unroll
            for (int nt = 0; nt < 4; ++nt) {
                const int c = wn * 32 + nt * 8 + g;
                bf[nt][0] = Bs[cur][(kb + tg) * BSTRIDE + c];
                bf[nt][1] = Bs[cur][(kb + tg + 4) * BSTRIDE + c];
            }
            #pragma unroll
            for (int mt = 0; mt < 4; ++mt)
                #pragma unroll
                for (int nt = 0; nt < 4; ++nt)
                    mma_tf32(acc[mt][nt], af[mt], bf[nt]);
        }
        if (more) {
            const int nxt = cur ^ 1;
            uint4 p;
            p = make_uint4(f2tf32(av0.x), f2tf32(av0.y), f2tf32(av0.z), f2tf32(av0.w));
            *(uint4*)&As[nxt][ar * ASTRIDE + ac] = p;
            p = make_uint4(f2tf32(av1.x), f2tf32(av1.y), f2tf32(av1.z), f2tf32(av1.w));
            *(uint4*)&As[nxt][(ar + 64) * ASTRIDE + ac] = p;
            p = make_uint4(f2tf32(bv0.x), f2tf32(bv0.y), f2tf32(bv0.z), f2tf32(bv0.w));
            *(uint4*)&Bs[nxt][bk * BSTRIDE + bc] = p;
            p = make_uint4(f2tf32(bv1.x), f2tf32(bv1.y), f2tf32(bv1.z), f2tf32(bv1.w));
            *(uint4*)&Bs[nxt][(bk + 8) * BSTRIDE + bc] = p;
            __syncthreads();
            cur = nxt;
        }
    }

    // --- epilogue: bias + optional residual ---
    #pragma unroll
    for (int mt = 0; mt < 4; ++mt) {
        const int gm = m0 + wm * 64 + mt * 16 + g;
        #pragma unroll
        for (int nt = 0; nt < 4; ++nt) {
            const int gn = n0 + wn * 32 + nt * 8 + 2 * tg;
            if (gn < N) {   // N even -> gn+1 also valid
                const float b0 = bias[gn], b1 = bias[gn + 1];
                float2 v0 = make_float2(acc[mt][nt][0] + b0, acc[mt][nt][1] + b1);
                float2 v1 = make_float2(acc[mt][nt][2] + b0, acc[mt][nt][3] + b1);
                const size_t i0 = (size_t)gm * N + gn;
                const size_t i1 = (size_t)(gm + 8) * N + gn;
                if (R) {
                    v0.x += R[i0];     v0.y += R[i0 + 1];
                    v1.x += R[i1];     v1.y += R[i1 + 1];
                }
                *(float2*)&C[i0] = v0;
                *(float2*)&C[i1] = v1;
            }
        }
    }
}

// ---------------- LayerNorm: one block per row of 768 ----------------------
__global__ void ln_kernel(const float* __restrict__ x, const float* __restrict__ w,
                          const float* __restrict__ b, float* __restrict__ y) {
    int row = blockIdx.x;
    const float* xr = x + (size_t)row * CC;
    float* yr = y + (size_t)row * CC;
    int t = threadIdx.x;                 // 256 threads, 3 elems each
    float v0 = xr[t], v1 = xr[t + 256], v2 = xr[t + 512];
    float s  = v0 + v1 + v2;
    float ss = v0*v0 + v1*v1 + v2*v2;
    __shared__ float red0[32], red1[32];
    #pragma unroll
    for (int o = 16; o; o >>= 1) {
        s  += __shfl_down_sync(0xffffffffu, s,  o);
        ss += __shfl_down_sync(0xffffffffu, ss, o);
    }
    int wid = t >> 5, lid = t & 31;
    if (lid == 0) { red0[wid] = s; red1[wid] = ss; }
    __syncthreads();
    if (wid == 0) {
        s  = (lid < 8) ? red0[lid] : 0.f;
        ss = (lid < 8) ? red1[lid] : 0.f;
        #pragma unroll
        for (int o = 4; o; o >>= 1) {
            s  += __shfl_down_sync(0xffffffffu, s,  o);
            ss += __shfl_down_sync(0xffffffffu, ss, o);
        }
        if (lid == 0) { red0[0] = s; red1[0] = ss; }
    }
    __syncthreads();
    float mean = red0[0] * (1.f / CC);
    float var  = red1[0] * (1.f / CC) - mean * mean;
    float inv  = rsqrtf(var + 1e-6f);
    yr[t]       = (v0 - mean) * inv * w[t]       + b[t];
    yr[t + 256] = (v1 - mean) * inv * w[t + 256] + b[t + 256];
    yr[t + 512] = (v2 - mean) * inv * w[t + 512] + b[t + 512];
}

// ---------------- pack so_w|aw_w into one [768,72] weight ------------------
__global__ void pack_kernel(const float* __restrict__ so_w, const float* __restrict__ so_b,
                            const float* __restrict__ aw_w, const float* __restrict__ aw_b,
                            float* __restrict__ w72, float* __restrict__ b72) {
    int i = blockIdx.x * 256 + threadIdx.x;
    if (i < CC * NOA) {
        int k = i / NOA, n = i % NOA;
        w72[i] = (n < 48) ? so_w[k * 48 + n] : aw_w[k * 24 + (n - 48)];
    }
    if (i < NOA) b72[i] = (i < 48) ? so_b[i] : aw_b[i - 48];
}

// ------- softmax(attn weights) + bilinear sample + weighted reduce ---------
__global__ void sample_kernel(const float* __restrict__ refp, float* __restrict__ attn) {
    int q = blockIdx.x;           // b*LQ + lq
    int b = q / LQ;
    __shared__ float cw[NH][NP][4];
    __shared__ int   ci[NH][NP][4];
    __shared__ float lg[NH * NP];
    int t = threadIdx.x;
    if (t < NH * NP) lg[t] = g_oa[(size_t)q * NOA + 48 + t];
    __syncthreads();
    if (t < NH * NP) {
        int h = t >> 2;
        float l0 = lg[h*4+0], l1 = lg[h*4+1], l2 = lg[h*4+2], l3 = lg[h*4+3];
        float m  = fmaxf(fmaxf(l0, l1), fmaxf(l2, l3));
        float e0 = __expf(l0-m), e1 = __expf(l1-m), e2 = __expf(l2-m), e3 = __expf(l3-m);
        float aw = __expf(lg[t]-m) / (e0 + e1 + e2 + e3);
        float rx = refp[(size_t)q * 2 + 0];
        float ry = refp[(size_t)q * 2 + 1];
        float ox = g_oa[(size_t)q * NOA + t*2 + 0];
        float oy = g_oa[(size_t)q * NOA + t*2 + 1];
        float x = (rx + ox * (1.f / WL)) * WL - 0.5f;
        float y = (ry + oy * (1.f / HL)) * HL - 0.5f;
        float x0f = floorf(x), y0f = floorf(y);
        float wx = x - x0f, wy = y - y0f;
        int x0 = (int)x0f, y0 = (int)y0f;
        float ws[4] = {(1.f-wy)*(1.f-wx), (1.f-wy)*wx, wy*(1.f-wx), wy*wx};
        const int dys[4] = {0,0,1,1}, dxs[4] = {0,1,0,1};
        int h2 = t >> 2, p = t & 3;
        #pragma unroll
        for (int c2 = 0; c2 < 4; c2++) {
            int xi = x0 + dxs[c2], yi = y0 + dys[c2];
            bool valid = (xi >= 0) && (xi < WL) && (yi >= 0) && (yi < HL);
            ci[h2][p][c2] = valid ? (yi * WL + xi) : -1;
            cw[h2][p][c2] = valid ? ws[c2] * aw : 0.f;
        }
    }
    __syncthreads();
    const float* vb = g_val + (size_t)b * LIN * CC;
    for (int c = t; c < CC; c += 256) {
        int h = c >> 7;
        float acc = 0.f;
        #pragma unroll
        for (int p = 0; p < NP; p++)
            #pragma unroll
            for (int c2 = 0; c2 < 4; c2++) {
                int idx = ci[h][p][c2];
                if (idx >= 0) acc += vb[(size_t)idx * CC + c] * cw[h][p][c2];
            }
        attn[(size_t)q * CC + c] = acc;
    }
}

// ---------- depthwise 3x3 conv (SAME, zero pad) + bias + exact GELU --------
__global__ void dwconv_gelu_kernel(const float* __restrict__ x, const float* __restrict__ w,
                                   const float* __restrict__ bias, float* __restrict__ y) {
    int pg = blockIdx.x;                 // 0 .. B*LQ-1
    int c  = threadIdx.x;                // 0 .. 191
    int b    = pg / LQ;
    int rem  = pg % LQ;
    int chunk = rem / (HH * WW);
    int pix   = rem % (HH * WW);
    int py = pix >> 5, px = pix & 31;
    const float* xb = x + ((size_t)b * LQ + (size_t)chunk * HH * WW) * HID;
    float acc = bias[c];
    #pragma unroll
    for (int dy = -1; dy <= 1; dy++) {
        int yy = py + dy;
        if (yy < 0 || yy >= HH) continue;
        #pragma unroll
        for (int dx = -1; dx <= 1; dx++) {
            int xx = px + dx;
            if (xx < 0 || xx >= WW) continue;
            acc += xb[(size_t)(yy * WW + xx) * HID + c] * w[c * 9 + (dy + 1) * 3 + (dx + 1)];
        }
    }
    y[(size_t)pg * HID + c] = 0.5f * acc * (1.f + erff(acc * 0.70710678118654752f));
}

// ---------------------------------------------------------------------------
extern "C" void kernel_launch(void* const* d_in, const int* in_sizes, int n_in,
                              void* d_out, int out_size) {
    const float* query = (const float*)d_in[0];
    const float* refp  = (const float*)d_in[1];
    const float* feat  = (const float*)d_in[2];
    const float* qn_w = (const float*)d_in[7];
    const float* qn_b = (const float*)d_in[8];
    const float* fn_w = (const float*)d_in[9];
    const float* fn_b = (const float*)d_in[10];
    const float* so_w = (const float*)d_in[11];
    const float* so_b = (const float*)d_in[12];
    const float* aw_w = (const float*)d_in[13];
    const float* aw_b = (const float*)d_in[14];
    const float* vp_w = (const float*)d_in[15];
    const float* vp_b = (const float*)d_in[16];
    const float* op_w = (const float*)d_in[17];
    const float* op_b = (const float*)d_in[18];
    const float* ffn_w = (const float*)d_in[19];
    const float* ffn_b = (const float*)d_in[20];
    const float* fc1_w = (const float*)d_in[21];
    const float* fc1_b = (const float*)d_in[22];
    const float* dw_w  = (const float*)d_in[23];
    const float* dw_b  = (const float*)d_in[24];
    const float* fc2_w = (const float*)d_in[25];
    const float* fc2_b = (const float*)d_in[26];
    float* out = (float*)d_out;

    float *p_qln, *p_fln, *p_val, *p_oa, *p_attn, *p_q2, *p_x1, *p_x2, *p_w72, *p_b72;
    cudaGetSymbolAddress((void**)&p_qln,  g_qln);
    cudaGetSymbolAddress((void**)&p_fln,  g_fln);
    cudaGetSymbolAddress((void**)&p_val,  g_val);
    cudaGetSymbolAddress((void**)&p_oa,   g_oa);
    cudaGetSymbolAddress((void**)&p_attn, g_attn);
    cudaGetSymbolAddress((void**)&p_q2,   g_q2);
    cudaGetSymbolAddress((void**)&p_x1,   g_x1);
    cudaGetSymbolAddress((void**)&p_x2,   g_x2);
    cudaGetSymbolAddress((void**)&p_w72,  g_w72);
    cudaGetSymbolAddress((void**)&p_b72,  g_b72);

    // 1. LayerNorms + weight packing
    ln_kernel<<<MQ, 256>>>(query, qn_w, qn_b, p_qln);
    ln_kernel<<<MF, 256>>>(feat,  fn_w, fn_b, p_fln);
    pack_kernel<<<(CC*NOA + 255)/256, 256>>>(so_w, so_b, aw_w, aw_b, p_w72, p_b72);

    // 2. value = f_ln @ vp_w + vp_b        (32768 x 768 x 768)
    gemm_tf32_kernel<<<dim3(CC/128, MF/128), 256>>>(p_fln, vp_w, vp_b, nullptr, p_val, MF, CC, CC);

    // 3. fused sampling-offset + attn-logit projection (24576 x 72 x 768)
    gemm_tf32_kernel<<<dim3(1, MQ/128), 256>>>(p_qln, p_w72, p_b72, nullptr, p_oa, MQ, NOA, CC);

    // 4. softmax + bilinear sample + head-reduce
    sample_kernel<<<MQ, 256>>>(refp, p_attn);

    // 5. output projection + residual -> q2   (24576 x 768 x 768)
    gemm_tf32_kernel<<<dim3(CC/128, MQ/128), 256>>>(p_attn, op_w, op_b, query, p_q2, MQ, CC, CC);

    // 6. ConvFFN
    ln_kernel<<<MQ, 256>>>(p_q2, ffn_w, ffn_b, p_qln);
    gemm_tf32_kernel<<<dim3((HID+127)/128, MQ/128), 256>>>(p_qln, fc1_w, fc1_b, nullptr, p_x1, MQ, HID, CC);
    dwconv_gelu_kernel<<<MQ, HID>>>(p_x1, dw_w, dw_b, p_x2);
    gemm_tf32_kernel<<<dim3(CC/128, MQ/128), 256>>>(p_x2, fc2_w, fc2_b, p_q2, out, MQ, CC, HID);
}

// round 3
// speedup vs baseline: 5.0483x; 1.2468x over previous
#include <cuda_runtime.h>
#include <math.h>
#include <stdint.h>

// ---------------- problem constants (fixed by setup_inputs) ----------------
#define BB   8
#define LQ   3072
#define CC   768
#define LIN  4096          // 64*64 feature tokens
#define HL   64
#define WL   64
#define NH   6
#define NP   4
#define HID  192
#define HH   32
#define WW   32
#define MQ   (BB*LQ)       // 24576
#define MF   (BB*LIN)      // 32768
#define NOA  72            // 48 offs + 24 attn logits, fused

// ---------------- scratch (device globals; no allocs allowed) --------------
__device__ float g_qln [MQ*CC];
__device__ float g_fln [MF*CC];
__device__ float g_val [MF*CC];
__device__ float g_oa  [MQ*NOA];
__device__ float g_attn[MQ*CC];
__device__ float g_q2  [MQ*CC];
__device__ float g_x1  [MQ*HID];
__device__ float g_x2  [MQ*HID];
__device__ float g_w72 [CC*NOA];
__device__ float g_b72 [NOA];

// ---------------- mma + cp.async helpers -----------------------------------
__device__ __forceinline__ void mma_tf32(float* d, const uint32_t* a, const uint32_t* b) {
    asm volatile(
        "mma.sync.aligned.m16n8k8.row.col.f32.tf32.tf32.f32 "
        "{%0,%1,%2,%3}, {%4,%5,%6,%7}, {%8,%9}, {%0,%1,%2,%3};\n"
        : "+f"(d[0]), "+f"(d[1]), "+f"(d[2]), "+f"(d[3])
        : "r"(a[0]), "r"(a[1]), "r"(a[2]), "r"(a[3]), "r"(b[0]), "r"(b[1]));
}
__device__ __forceinline__ void cp16(uint32_t dst, const void* src, bool valid) {
    int sz = valid ? 16 : 0;
    asm volatile("cp.async.cg.shared.global [%0], [%1], 16, %2;\n"
                 :: "r"(dst), "l"(src), "r"(sz));
}
__device__ __forceinline__ void cp_commit() { asm volatile("cp.async.commit_group;\n"); }
template <int N> __device__ __forceinline__ void cp_wait() {
    asm volatile("cp.async.wait_group %0;\n" :: "n"(N));
}

// ---------------- tf32 tensor-core GEMM: C = A*W + bias (+R) ---------------
// BM=128, BN=128, BK=16, 256 threads, warps 2(m) x 4(n), warp tile 64x32.
// fp32 fed raw into tf32 MMA (HW truncates mantissa). 4-stage cp.async pipe.
#define ASTRIDE 20          // 16 + 4 pad  -> conflict-free A-fragment LDS
#define BSTRIDE 136         // 128 + 8 pad -> conflict-free B-fragment LDS
#define ASZ (128 * ASTRIDE) // 2560 u32
#define BSZ (16 * BSTRIDE)  // 2176 u32
#define SSZ (ASZ + BSZ)     // 4736 u32 per stage
#define NSTAGE 4
#define GEMM_SMEM (NSTAGE * SSZ * 4)

__global__ __launch_bounds__(256)
void gemm_tf32_kernel(const float* __restrict__ A, const float* __restrict__ W,
                      const float* __restrict__ bias, const float* __restrict__ R,
                      float* __restrict__ C, int M, int N, int K) {
    extern __shared__ uint32_t sm[];

    const int t    = threadIdx.x;
    const int lane = t & 31;
    const int g    = lane >> 2;      // groupID 0..7
    const int tg   = lane & 3;       // thread-in-group 0..3
    const int wid  = t >> 5;
    const int wm   = wid & 1;        // m offset wm*64
    const int wn   = wid >> 1;       // n offset wn*32

    const int m0 = blockIdx.y * 128;
    const int n0 = blockIdx.x * 128;

    // staging coordinates
    const int ar  = t >> 2;          // A rows ar, ar+64
    const int ac  = (t & 3) * 4;     // A col offset within BK
    const int bk  = t >> 5;          // B k-rows bk, bk+8
    const int bc  = (t & 31) * 4;    // B col offset within BN
    const int nb  = n0 + bc;
    const bool bvalid = (nb < N);
    const int nbs = bvalid ? nb : 0;

    const uint32_t smem_u = (uint32_t)__cvta_generic_to_shared(sm);
    const uint32_t a_off0 = (ar * ASTRIDE + ac) * 4;
    const uint32_t a_off1 = ((ar + 64) * ASTRIDE + ac) * 4;
    const uint32_t b_off0 = (ASZ + bk * BSTRIDE + bc) * 4;
    const uint32_t b_off1 = (ASZ + (bk + 8) * BSTRIDE + bc) * 4;

    const float* Abase = A + (size_t)(m0 + ar) * K + ac;
    const float* Bbase = W + (size_t)bk * N + nbs;

    const int KT = K >> 4;

    // issue copy for k-chunk `ck` into stage buffer `s`
    auto issue = [&](int ck, int s) {
        const uint32_t sb = smem_u + (uint32_t)(s * SSZ * 4);
        const float* Ap = Abase + ck * 16;
        cp16(sb + a_off0, Ap, true);
        cp16(sb + a_off1, Ap + (size_t)64 * K, true);
        const float* Bp = Bbase + (size_t)ck * 16 * N;
        cp16(sb + b_off0, Bp, bvalid);
        cp16(sb + b_off1, Bp + (size_t)8 * N, bvalid);
    };

    // prologue: fill stages 0..NSTAGE-2
    #pragma unroll
    for (int s = 0; s < NSTAGE - 1; ++s) {
        if (s < KT) issue(s, s);
        cp_commit();
    }
    cp_wait<NSTAGE - 2>();
    __syncthreads();

    float acc[4][4][4] = {};

    for (int it = 0; it < KT; ++it) {
        const int cur = it & (NSTAGE - 1);
        const uint32_t* Ab = sm + cur * SSZ;
        const uint32_t* Bb = sm + cur * SSZ + ASZ;

        #pragma unroll
        for (int ks = 0; ks < 2; ++ks) {
            const int kb = ks * 8;
            uint32_t af[4][4], bf[4][2];
            #pragma unroll
            for (int mt = 0; mt < 4; ++mt) {
                const int r = wm * 64 + mt * 16 + g;
                af[mt][0] = Ab[r * ASTRIDE + kb + tg];
                af[mt][1] = Ab[(r + 8) * ASTRIDE + kb + tg];
                af[mt][2] = Ab[r * ASTRIDE + kb + tg + 4];
                af[mt][3] = Ab[(r + 8) * ASTRIDE + kb + tg + 4];
            }
            #pragma unroll
            for (int nt = 0; nt < 4; ++nt) {
                const int c = wn * 32 + nt * 8 + g;
                bf[nt][0] = Bb[(kb + tg) * BSTRIDE + c];
                bf[nt][1] = Bb[(kb + tg + 4) * BSTRIDE + c];
            }
            #pragma unroll
            for (int mt = 0; mt < 4; ++mt)
                #pragma unroll
                for (int nt = 0; nt < 4; ++nt)
                    mma_tf32(acc[mt][nt], af[mt], bf[nt]);
        }

        const int nk = it + NSTAGE - 1;
        if (nk < KT) issue(nk, nk & (NSTAGE - 1));
        cp_commit();
        cp_wait<NSTAGE - 2>();
        __syncthreads();
    }

    // epilogue: bias + optional residual
    #pragma unroll
    for (int mt = 0; mt < 4; ++mt) {
        const int gm = m0 + wm * 64 + mt * 16 + g;
        #pragma unroll
        for (int nt = 0; nt < 4; ++nt) {
            const int gn = n0 + wn * 32 + nt * 8 + 2 * tg;
            if (gn < N) {
                const float b0 = bias[gn], b1 = bias[gn + 1];
                float2 v0 = make_float2(acc[mt][nt][0] + b0, acc[mt][nt][1] + b1);
                float2 v1 = make_float2(acc[mt][nt][2] + b0, acc[mt][nt][3] + b1);
                const size_t i0 = (size_t)gm * N + gn;
                const size_t i1 = (size_t)(gm + 8) * N + gn;
                if (R) {
                    v0.x += R[i0];     v0.y += R[i0 + 1];
                    v1.x += R[i1];     v1.y += R[i1 + 1];
                }
                *(float2*)&C[i0] = v0;
                *(float2*)&C[i1] = v1;
            }
        }
    }
}

// ---------------- LayerNorm: one block per row, float4 ---------------------
__global__ void ln_kernel(const float* __restrict__ x, const float* __restrict__ w,
                          const float* __restrict__ b, float* __restrict__ y) {
    const int row = blockIdx.x;
    const int t = threadIdx.x;          // 192 threads, one float4 each
    const float4 v = ((const float4*)(x + (size_t)row * CC))[t];
    float s  = v.x + v.y + v.z + v.w;
    float ss = v.x*v.x + v.y*v.y + v.z*v.z + v.w*v.w;
    __shared__ float red0[6], red1[6];
    #pragma unroll
    for (int o = 16; o; o >>= 1) {
        s  += __shfl_down_sync(0xffffffffu, s,  o);
        ss += __shfl_down_sync(0xffffffffu, ss, o);
    }
    if ((t & 31) == 0) { red0[t >> 5] = s; red1[t >> 5] = ss; }
    __syncthreads();
    float st = 0.f, sst = 0.f;
    #pragma unroll
    for (int i = 0; i < 6; ++i) { st += red0[i]; sst += red1[i]; }
    const float mean = st * (1.f / CC);
    const float var  = sst * (1.f / CC) - mean * mean;
    const float inv  = rsqrtf(var + 1e-6f);
    const float4 wv = ((const float4*)w)[t];
    const float4 bv = ((const float4*)b)[t];
    float4 o;
    o.x = (v.x - mean) * inv * wv.x + bv.x;
    o.y = (v.y - mean) * inv * wv.y + bv.y;
    o.z = (v.z - mean) * inv * wv.z + bv.z;
    o.w = (v.w - mean) * inv * wv.w + bv.w;
    ((float4*)(y + (size_t)row * CC))[t] = o;
}

// ---------------- pack so_w|aw_w into one [768,72] weight ------------------
__global__ void pack_kernel(const float* __restrict__ so_w, const float* __restrict__ so_b,
                            const float* __restrict__ aw_w, const float* __restrict__ aw_b,
                            float* __restrict__ w72, float* __restrict__ b72) {
    int i = blockIdx.x * 256 + threadIdx.x;
    if (i < CC * NOA) {
        int k = i / NOA, n = i % NOA;
        w72[i] = (n < 48) ? so_w[k * 48 + n] : aw_w[k * 24 + (n - 48)];
    }
    if (i < NOA) b72[i] = (i < 48) ? so_b[i] : aw_b[i - 48];
}

// ------- softmax(attn weights) + bilinear sample + weighted reduce ---------
// One block per query; 192 threads, float4 channels.
__global__ void sample_kernel(const float* __restrict__ refp, float* __restrict__ attn) {
    int q = blockIdx.x;           // b*LQ + lq
    int b = q / LQ;
    __shared__ float cw[NH][NP][4];
    __shared__ int   ci[NH][NP][4];
    __shared__ float lg[NH * NP];
    int t = threadIdx.x;
    if (t < NH * NP) lg[t] = g_oa[(size_t)q * NOA + 48 + t];
    __syncthreads();
    if (t < NH * NP) {
        int h = t >> 2;
        float l0 = lg[h*4+0], l1 = lg[h*4+1], l2 = lg[h*4+2], l3 = lg[h*4+3];
        float m  = fmaxf(fmaxf(l0, l1), fmaxf(l2, l3));
        float e0 = __expf(l0-m), e1 = __expf(l1-m), e2 = __expf(l2-m), e3 = __expf(l3-m);
        float aw = __expf(lg[t]-m) / (e0 + e1 + e2 + e3);
        float rx = refp[(size_t)q * 2 + 0];
        float ry = refp[(size_t)q * 2 + 1];
        float ox = g_oa[(size_t)q * NOA + t*2 + 0];
        float oy = g_oa[(size_t)q * NOA + t*2 + 1];
        float x = (rx + ox * (1.f / WL)) * WL - 0.5f;
        float y = (ry + oy * (1.f / HL)) * HL - 0.5f;
        float x0f = floorf(x), y0f = floorf(y);
        float wx = x - x0f, wy = y - y0f;
        int x0 = (int)x0f, y0 = (int)y0f;
        float ws[4] = {(1.f-wy)*(1.f-wx), (1.f-wy)*wx, wy*(1.f-wx), wy*wx};
        const int dys[4] = {0,0,1,1}, dxs[4] = {0,1,0,1};
        int h2 = t >> 2, p = t & 3;
        #pragma unroll
        for (int c2 = 0; c2 < 4; c2++) {
            int xi = x0 + dxs[c2], yi = y0 + dys[c2];
            bool valid = (xi >= 0) && (xi < WL) && (yi >= 0) && (yi < HL);
            ci[h2][p][c2] = valid ? (yi * WL + xi) : -1;
            cw[h2][p][c2] = valid ? ws[c2] * aw : 0.f;
        }
    }
    __syncthreads();
    const float* vb = g_val + (size_t)b * LIN * CC;
    const int h = t >> 5;                 // (t*4) >> 7
    float4 acc = make_float4(0.f, 0.f, 0.f, 0.f);
    #pragma unroll
    for (int p = 0; p < NP; p++)
        #pragma unroll
        for (int c2 = 0; c2 < 4; c2++) {
            int idx = ci[h][p][c2];
            if (idx >= 0) {
                float wgt = cw[h][p][c2];
                float4 v = ((const float4*)(vb + (size_t)idx * CC))[t];
                acc.x += v.x * wgt; acc.y += v.y * wgt;
                acc.z += v.z * wgt; acc.w += v.w * wgt;
            }
        }
    ((float4*)(attn + (size_t)q * CC))[t] = acc;
}

// ---------- depthwise 3x3 conv (SAME, zero pad) + bias + exact GELU --------
__global__ void dwconv_gelu_kernel(const float* __restrict__ x, const float* __restrict__ w,
                                   const float* __restrict__ bias, float* __restrict__ y) {
    int pg = blockIdx.x;                 // 0 .. B*LQ-1
    int c  = threadIdx.x;                // 0 .. 191
    int b    = pg / LQ;
    int rem  = pg % LQ;
    int chunk = rem / (HH * WW);
    int pix   = rem % (HH * WW);
    int py = pix >> 5, px = pix & 31;
    const float* xb = x + ((size_t)b * LQ + (size_t)chunk * HH * WW) * HID;
    float acc = bias[c];
    #pragma unroll
    for (int dy = -1; dy <= 1; dy++) {
        int yy = py + dy;
        if (yy < 0 || yy >= HH) continue;
        #pragma unroll
        for (int dx = -1; dx <= 1; dx++) {
            int xx = px + dx;
            if (xx < 0 || xx >= WW) continue;
            acc += xb[(size_t)(yy * WW + xx) * HID + c] * w[c * 9 + (dy + 1) * 3 + (dx + 1)];
        }
    }
    y[(size_t)pg * HID + c] = 0.5f * acc * (1.f + erff(acc * 0.70710678118654752f));
}

// ---------------------------------------------------------------------------
extern "C" void kernel_launch(void* const* d_in, const int* in_sizes, int n_in,
                              void* d_out, int out_size) {
    const float* query = (const float*)d_in[0];
    const float* refp  = (const float*)d_in[1];
    const float* feat  = (const float*)d_in[2];
    const float* qn_w = (const float*)d_in[7];
    const float* qn_b = (const float*)d_in[8];
    const float* fn_w = (const float*)d_in[9];
    const float* fn_b = (const float*)d_in[10];
    const float* so_w = (const float*)d_in[11];
    const float* so_b = (const float*)d_in[12];
    const float* aw_w = (const float*)d_in[13];
    const float* aw_b = (const float*)d_in[14];
    const float* vp_w = (const float*)d_in[15];
    const float* vp_b = (const float*)d_in[16];
    const float* op_w = (const float*)d_in[17];
    const float* op_b = (const float*)d_in[18];
    const float* ffn_w = (const float*)d_in[19];
    const float* ffn_b = (const float*)d_in[20];
    const float* fc1_w = (const float*)d_in[21];
    const float* fc1_b = (const float*)d_in[22];
    const float* dw_w  = (const float*)d_in[23];
    const float* dw_b  = (const float*)d_in[24];
    const float* fc2_w = (const float*)d_in[25];
    const float* fc2_b = (const float*)d_in[26];
    float* out = (float*)d_out;

    float *p_qln, *p_fln, *p_val, *p_oa, *p_attn, *p_q2, *p_x1, *p_x2, *p_w72, *p_b72;
    cudaGetSymbolAddress((void**)&p_qln,  g_qln);
    cudaGetSymbolAddress((void**)&p_fln,  g_fln);
    cudaGetSymbolAddress((void**)&p_val,  g_val);
    cudaGetSymbolAddress((void**)&p_oa,   g_oa);
    cudaGetSymbolAddress((void**)&p_attn, g_attn);
    cudaGetSymbolAddress((void**)&p_q2,   g_q2);
    cudaGetSymbolAddress((void**)&p_x1,   g_x1);
    cudaGetSymbolAddress((void**)&p_x2,   g_x2);
    cudaGetSymbolAddress((void**)&p_w72,  g_w72);
    cudaGetSymbolAddress((void**)&p_b72,  g_b72);

    cudaFuncSetAttribute(gemm_tf32_kernel, cudaFuncAttributeMaxDynamicSharedMemorySize, GEMM_SMEM);

    // 1. LayerNorms + weight packing
    ln_kernel<<<MQ, 192>>>(query, qn_w, qn_b, p_qln);
    ln_kernel<<<MF, 192>>>(feat,  fn_w, fn_b, p_fln);
    pack_kernel<<<(CC*NOA + 255)/256, 256>>>(so_w, so_b, aw_w, aw_b, p_w72, p_b72);

    // 2. value = f_ln @ vp_w + vp_b        (32768 x 768 x 768)
    gemm_tf32_kernel<<<dim3(CC/128, MF/128), 256, GEMM_SMEM>>>(p_fln, vp_w, vp_b, nullptr, p_val, MF, CC, CC);

    // 3. fused sampling-offset + attn-logit projection (24576 x 72 x 768)
    gemm_tf32_kernel<<<dim3(1, MQ/128), 256, GEMM_SMEM>>>(p_qln, p_w72, p_b72, nullptr, p_oa, MQ, NOA, CC);

    // 4. softmax + bilinear sample + head-reduce
    sample_kernel<<<MQ, 192>>>(refp, p_attn);

    // 5. output projection + residual -> q2   (24576 x 768 x 768)
    gemm_tf32_kernel<<<dim3(CC/128, MQ/128), 256, GEMM_SMEM>>>(p_attn, op_w, op_b, query, p_q2, MQ, CC, CC);

    // 6. ConvFFN
    ln_kernel<<<MQ, 192>>>(p_q2, ffn_w, ffn_b, p_qln);
    gemm_tf32_kernel<<<dim3((HID+127)/128, MQ/128), 256, GEMM_SMEM>>>(p_qln, fc1_w, fc1_b, nullptr, p_x1, MQ, HID, CC);
    dwconv_gelu_kernel<<<MQ, HID>>>(p_x1, dw_w, dw_b, p_x2);
    gemm_tf32_kernel<<<dim3(CC/128, MQ/128), 256, GEMM_SMEM>>>(p_x2, fc2_w, fc2_b, p_q2, out, MQ, CC, HID);
}

// round 4
// speedup vs baseline: 5.1343x; 1.0170x over previous
#include <cuda_runtime.h>
#include <math.h>
#include <stdint.h>

// ---------------- problem constants (fixed by setup_inputs) ----------------
#define BB   8
#define LQ   3072
#define CC   768
#define LIN  4096          // 64*64 feature tokens
#define HL   64
#define WL   64
#define NH   6
#define NP   4
#define HID  192
#define HH   32
#define WW   32
#define MQ   (BB*LQ)       // 24576
#define MF   (BB*LIN)      // 32768
#define NOA  72            // 48 offs + 24 attn logits, fused

// ---------------- scratch (device globals; no allocs allowed) --------------
__device__ float g_qln [MQ*CC];
__device__ float g_fln [MF*CC];
__device__ float g_val [MF*CC];
__device__ float g_oa  [MQ*NOA];
__device__ float g_attn[MQ*CC];
__device__ float g_q2  [MQ*CC];
__device__ float g_x1  [MQ*HID];
__device__ float g_x2  [MQ*HID];
__device__ float g_w72 [CC*NOA];
__device__ float g_b72 [NOA];

// ---------------- mma + cp.async helpers -----------------------------------
__device__ __forceinline__ void mma_tf32(float* d, const uint32_t* a, const uint32_t* b) {
    asm volatile(
        "mma.sync.aligned.m16n8k8.row.col.f32.tf32.tf32.f32 "
        "{%0,%1,%2,%3}, {%4,%5,%6,%7}, {%8,%9}, {%0,%1,%2,%3};\n"
        : "+f"(d[0]), "+f"(d[1]), "+f"(d[2]), "+f"(d[3])
        : "r"(a[0]), "r"(a[1]), "r"(a[2]), "r"(a[3]), "r"(b[0]), "r"(b[1]));
}
__device__ __forceinline__ void cp16(uint32_t dst, const void* src, bool valid) {
    int sz = valid ? 16 : 0;
    asm volatile("cp.async.cg.shared.global [%0], [%1], 16, %2;\n"
                 :: "r"(dst), "l"(src), "r"(sz));
}
__device__ __forceinline__ void cp_commit() { asm volatile("cp.async.commit_group;\n"); }
template <int N> __device__ __forceinline__ void cp_wait() {
    asm volatile("cp.async.wait_group %0;\n" :: "n"(N));
}

// ---------------- tf32 tensor-core GEMM: C = A*W + bias (+R) ---------------
// BM=128, BN=128, BK=32, 256 threads, warps 2(m) x 4(n), warp tile 64x32.
// fp32 fed raw into tf32 MMA (HW truncates mantissa). 3-stage cp.async pipe.
#define ASTRIDE 36          // 32 + 4 pad  -> conflict-free A-fragment LDS
#define BSTRIDE 136         // 128 + 8 pad -> conflict-free B-fragment LDS
#define ASZ (128 * ASTRIDE) // 4608 u32
#define BSZ (32 * BSTRIDE)  // 4352 u32
#define SSZ (ASZ + BSZ)     // 8960 u32 per stage
#define NSTAGE 3
#define GEMM_SMEM (NSTAGE * SSZ * 4)   // 107,520 B

__global__ __launch_bounds__(256, 2)
void gemm_tf32_kernel(const float* __restrict__ A, const float* __restrict__ W,
                      const float* __restrict__ bias, const float* __restrict__ R,
                      float* __restrict__ C, int M, int N, int K) {
    extern __shared__ uint32_t sm[];

    const int t    = threadIdx.x;
    const int lane = t & 31;
    const int g    = lane >> 2;      // groupID 0..7
    const int tg   = lane & 3;       // thread-in-group 0..3
    const int wid  = t >> 5;
    const int wm   = wid & 1;        // m offset wm*64
    const int wn   = wid >> 1;       // n offset wn*32

    const int m0 = blockIdx.y * 128;
    const int n0 = blockIdx.x * 128;

    // staging coordinates (BK=32)
    const int ra  = t >> 3;          // A rows ra + 32j, j=0..3
    const int ca  = (t & 7) * 4;     // A col offset within BK
    const int kb0 = t >> 5;          // B k-rows kb0 + 8j, j=0..3
    const int cb  = (t & 31) * 4;    // B col offset within BN
    const int nb  = n0 + cb;
    const bool bvalid = (nb < N);
    const int nbs = bvalid ? nb : 0;

    const uint32_t smem_u = (uint32_t)__cvta_generic_to_shared(sm);
    uint32_t a_off[4], b_off[4];
    #pragma unroll
    for (int j = 0; j < 4; ++j) {
        a_off[j] = ((ra + 32 * j) * ASTRIDE + ca) * 4;
        b_off[j] = (ASZ + (kb0 + 8 * j) * BSTRIDE + cb) * 4;
    }
    const float* Abase = A + (size_t)(m0 + ra) * K + ca;
    const float* Bbase = W + (size_t)kb0 * N + nbs;

    const int KT = K >> 5;           // chunks of 32 (K=768->24, K=192->6)

    auto issue = [&](int ck, int s) {
        const uint32_t sb = smem_u + (uint32_t)(s * SSZ * 4);
        const float* Ap = Abase + ck * 32;
        const float* Bp = Bbase + (size_t)ck * 32 * N;
        #pragma unroll
        for (int j = 0; j < 4; ++j)
            cp16(sb + a_off[j], Ap + (size_t)(32 * j) * K, true);
        #pragma unroll
        for (int j = 0; j < 4; ++j)
            cp16(sb + b_off[j], Bp + (size_t)(8 * j) * N, bvalid);
    };

    // prologue: stages 0,1
    issue(0, 0); cp_commit();
    issue(1, 1); cp_commit();

    float acc[4][4][4] = {};

    for (int it = 0; it < KT; ++it) {
        cp_wait<1>();
        __syncthreads();

        const int nk = it + 2;
        if (nk < KT) { issue(nk, nk % NSTAGE); }
        cp_commit();

        const int cur = it % NSTAGE;
        const uint32_t* Ab = sm + cur * SSZ;
        const uint32_t* Bb = sm + cur * SSZ + ASZ;

        #pragma unroll
        for (int ks = 0; ks < 4; ++ks) {
            const int kb = ks * 8;
            uint32_t af[4][4], bf[4][2];
            #pragma unroll
            for (int mt = 0; mt < 4; ++mt) {
                const int r = wm * 64 + mt * 16 + g;
                af[mt][0] = Ab[r * ASTRIDE + kb + tg];
                af[mt][1] = Ab[(r + 8) * ASTRIDE + kb + tg];
                af[mt][2] = Ab[r * ASTRIDE + kb + tg + 4];
                af[mt][3] = Ab[(r + 8) * ASTRIDE + kb + tg + 4];
            }
            #pragma unroll
            for (int nt = 0; nt < 4; ++nt) {
                const int c = wn * 32 + nt * 8 + g;
                bf[nt][0] = Bb[(kb + tg) * BSTRIDE + c];
                bf[nt][1] = Bb[(kb + tg + 4) * BSTRIDE + c];
            }
            #pragma unroll
            for (int mt = 0; mt < 4; ++mt)
                #pragma unroll
                for (int nt = 0; nt < 4; ++nt)
                    mma_tf32(acc[mt][nt], af[mt], bf[nt]);
        }
        __syncthreads();   // all warps done with `cur` before it is overwritten
    }

    // epilogue: bias + optional residual
    #pragma unroll
    for (int mt = 0; mt < 4; ++mt) {
        const int gm = m0 + wm * 64 + mt * 16 + g;
        #pragma unroll
        for (int nt = 0; nt < 4; ++nt) {
            const int gn = n0 + wn * 32 + nt * 8 + 2 * tg;
            if (gn < N) {
                const float b0 = bias[gn], b1 = bias[gn + 1];
                float2 v0 = make_float2(acc[mt][nt][0] + b0, acc[mt][nt][1] + b1);
                float2 v1 = make_float2(acc[mt][nt][2] + b0, acc[mt][nt][3] + b1);
                const size_t i0 = (size_t)gm * N + gn;
                const size_t i1 = (size_t)(gm + 8) * N + gn;
                if (R) {
                    v0.x += R[i0];     v0.y += R[i0 + 1];
                    v1.x += R[i1];     v1.y += R[i1 + 1];
                }
                *(float2*)&C[i0] = v0;
                *(float2*)&C[i1] = v1;
            }
        }
    }
}

// ---------------- LayerNorm: one block per row, float4 ---------------------
__global__ void ln_kernel(const float* __restrict__ x, const float* __restrict__ w,
                          const float* __restrict__ b, float* __restrict__ y) {
    const int row = blockIdx.x;
    const int t = threadIdx.x;          // 192 threads, one float4 each
    const float4 v = ((const float4*)(x + (size_t)row * CC))[t];
    float s  = v.x + v.y + v.z + v.w;
    float ss = v.x*v.x + v.y*v.y + v.z*v.z + v.w*v.w;
    __shared__ float red0[6], red1[6];
    #pragma unroll
    for (int o = 16; o; o >>= 1) {
        s  += __shfl_down_sync(0xffffffffu, s,  o);
        ss += __shfl_down_sync(0xffffffffu, ss, o);
    }
    if ((t & 31) == 0) { red0[t >> 5] = s; red1[t >> 5] = ss; }
    __syncthreads();
    float st = 0.f, sst = 0.f;
    #pragma unroll
    for (int i = 0; i < 6; ++i) { st += red0[i]; sst += red1[i]; }
    const float mean = st * (1.f / CC);
    const float var  = sst * (1.f / CC) - mean * mean;
    const float inv  = rsqrtf(var + 1e-6f);
    const float4 wv = ((const float4*)w)[t];
    const float4 bv = ((const float4*)b)[t];
    float4 o;
    o.x = (v.x - mean) * inv * wv.x + bv.x;
    o.y = (v.y - mean) * inv * wv.y + bv.y;
    o.z = (v.z - mean) * inv * wv.z + bv.z;
    o.w = (v.w - mean) * inv * wv.w + bv.w;
    ((float4*)(y + (size_t)row * CC))[t] = o;
}

// ---------------- pack so_w|aw_w into one [768,72] weight ------------------
__global__ void pack_kernel(const float* __restrict__ so_w, const float* __restrict__ so_b,
                            const float* __restrict__ aw_w, const float* __restrict__ aw_b,
                            float* __restrict__ w72, float* __restrict__ b72) {
    int i = blockIdx.x * 256 + threadIdx.x;
    if (i < CC * NOA) {
        int k = i / NOA, n = i % NOA;
        w72[i] = (n < 48) ? so_w[k * 48 + n] : aw_w[k * 24 + (n - 48)];
    }
    if (i < NOA) b72[i] = (i < 48) ? so_b[i] : aw_b[i - 48];
}

// ------- softmax(attn weights) + bilinear sample + weighted reduce ---------
__global__ void sample_kernel(const float* __restrict__ refp, float* __restrict__ attn) {
    int q = blockIdx.x;           // b*LQ + lq
    int b = q / LQ;
    __shared__ float cw[NH][NP][4];
    __shared__ int   ci[NH][NP][4];
    __shared__ float lg[NH * NP];
    int t = threadIdx.x;
    if (t < NH * NP) lg[t] = g_oa[(size_t)q * NOA + 48 + t];
    __syncthreads();
    if (t < NH * NP) {
        int h = t >> 2;
        float l0 = lg[h*4+0], l1 = lg[h*4+1], l2 = lg[h*4+2], l3 = lg[h*4+3];
        float m  = fmaxf(fmaxf(l0, l1), fmaxf(l2, l3));
        float e0 = __expf(l0-m), e1 = __expf(l1-m), e2 = __expf(l2-m), e3 = __expf(l3-m);
        float aw = __expf(lg[t]-m) / (e0 + e1 + e2 + e3);
        float rx = refp[(size_t)q * 2 + 0];
        float ry = refp[(size_t)q * 2 + 1];
        float ox = g_oa[(size_t)q * NOA + t*2 + 0];
        float oy = g_oa[(size_t)q * NOA + t*2 + 1];
        float x = (rx + ox * (1.f / WL)) * WL - 0.5f;
        float y = (ry + oy * (1.f / HL)) * HL - 0.5f;
        float x0f = floorf(x), y0f = floorf(y);
        float wx = x - x0f, wy = y - y0f;
        int x0 = (int)x0f, y0 = (int)y0f;
        float ws[4] = {(1.f-wy)*(1.f-wx), (1.f-wy)*wx, wy*(1.f-wx), wy*wx};
        const int dys[4] = {0,0,1,1}, dxs[4] = {0,1,0,1};
        int h2 = t >> 2, p = t & 3;
        #pragma unroll
        for (int c2 = 0; c2 < 4; c2++) {
            int xi = x0 + dxs[c2], yi = y0 + dys[c2];
            bool valid = (xi >= 0) && (xi < WL) && (yi >= 0) && (yi < HL);
            ci[h2][p][c2] = valid ? (yi * WL + xi) : -1;
            cw[h2][p][c2] = valid ? ws[c2] * aw : 0.f;
        }
    }
    __syncthreads();
    const float* vb = g_val + (size_t)b * LIN * CC;
    const int h = t >> 5;                 // (t*4) >> 7
    float4 acc = make_float4(0.f, 0.f, 0.f, 0.f);
    #pragma unroll
    for (int p = 0; p < NP; p++)
        #pragma unroll
        for (int c2 = 0; c2 < 4; c2++) {
            int idx = ci[h][p][c2];
            if (idx >= 0) {
                float wgt = cw[h][p][c2];
                float4 v = ((const float4*)(vb + (size_t)idx * CC))[t];
                acc.x += v.x * wgt; acc.y += v.y * wgt;
                acc.z += v.z * wgt; acc.w += v.w * wgt;
            }
        }
    ((float4*)(attn + (size_t)q * CC))[t] = acc;
}

// ---------- depthwise 3x3 conv (SAME, zero pad) + bias + exact GELU --------
__global__ void dwconv_gelu_kernel(const float* __restrict__ x, const float* __restrict__ w,
                                   const float* __restrict__ bias, float* __restrict__ y) {
    int pg = blockIdx.x;                 // 0 .. B*LQ-1
    int c  = threadIdx.x;                // 0 .. 191
    int b    = pg / LQ;
    int rem  = pg % LQ;
    int chunk = rem / (HH * WW);
    int pix   = rem % (HH * WW);
    int py = pix >> 5, px = pix & 31;
    const float* xb = x + ((size_t)b * LQ + (size_t)chunk * HH * WW) * HID;
    float acc = bias[c];
    #pragma unroll
    for (int dy = -1; dy <= 1; dy++) {
        int yy = py + dy;
        if (yy < 0 || yy >= HH) continue;
        #pragma unroll
        for (int dx = -1; dx <= 1; dx++) {
            int xx = px + dx;
            if (xx < 0 || xx >= WW) continue;
            acc += xb[(size_t)(yy * WW + xx) * HID + c] * w[c * 9 + (dy + 1) * 3 + (dx + 1)];
        }
    }
    y[(size_t)pg * HID + c] = 0.5f * acc * (1.f + erff(acc * 0.70710678118654752f));
}

// ---------------------------------------------------------------------------
extern "C" void kernel_launch(void* const* d_in, const int* in_sizes, int n_in,
                              void* d_out, int out_size) {
    const float* query = (const float*)d_in[0];
    const float* refp  = (const float*)d_in[1];
    const float* feat  = (const float*)d_in[2];
    const float* qn_w = (const float*)d_in[7];
    const float* qn_b = (const float*)d_in[8];
    const float* fn_w = (const float*)d_in[9];
    const float* fn_b = (const float*)d_in[10];
    const float* so_w = (const float*)d_in[11];
    const float* so_b = (const float*)d_in[12];
    const float* aw_w = (const float*)d_in[13];
    const float* aw_b = (const float*)d_in[14];
    const float* vp_w = (const float*)d_in[15];
    const float* vp_b = (const float*)d_in[16];
    const float* op_w = (const float*)d_in[17];
    const float* op_b = (const float*)d_in[18];
    const float* ffn_w = (const float*)d_in[19];
    const float* ffn_b = (const float*)d_in[20];
    const float* fc1_w = (const float*)d_in[21];
    const float* fc1_b = (const float*)d_in[22];
    const float* dw_w  = (const float*)d_in[23];
    const float* dw_b  = (const float*)d_in[24];
    const float* fc2_w = (const float*)d_in[25];
    const float* fc2_b = (const float*)d_in[26];
    float* out = (float*)d_out;

    float *p_qln, *p_fln, *p_val, *p_oa, *p_attn, *p_q2, *p_x1, *p_x2, *p_w72, *p_b72;
    cudaGetSymbolAddress((void**)&p_qln,  g_qln);
    cudaGetSymbolAddress((void**)&p_fln,  g_fln);
    cudaGetSymbolAddress((void**)&p_val,  g_val);
    cudaGetSymbolAddress((void**)&p_oa,   g_oa);
    cudaGetSymbolAddress((void**)&p_attn, g_attn);
    cudaGetSymbolAddress((void**)&p_q2,   g_q2);
    cudaGetSymbolAddress((void**)&p_x1,   g_x1);
    cudaGetSymbolAddress((void**)&p_x2,   g_x2);
    cudaGetSymbolAddress((void**)&p_w72,  g_w72);
    cudaGetSymbolAddress((void**)&p_b72,  g_b72);

    cudaFuncSetAttribute(gemm_tf32_kernel, cudaFuncAttributeMaxDynamicSharedMemorySize, GEMM_SMEM);

    // 1. LayerNorms + weight packing
    ln_kernel<<<MQ, 192>>>(query, qn_w, qn_b, p_qln);
    ln_kernel<<<MF, 192>>>(feat,  fn_w, fn_b, p_fln);
    pack_kernel<<<(CC*NOA + 255)/256, 256>>>(so_w, so_b, aw_w, aw_b, p_w72, p_b72);

    // 2. value = f_ln @ vp_w + vp_b        (32768 x 768 x 768)
    gemm_tf32_kernel<<<dim3(CC/128, MF/128), 256, GEMM_SMEM>>>(p_fln, vp_w, vp_b, nullptr, p_val, MF, CC, CC);

    // 3. fused sampling-offset + attn-logit projection (24576 x 72 x 768)
    gemm_tf32_kernel<<<dim3(1, MQ/128), 256, GEMM_SMEM>>>(p_qln, p_w72, p_b72, nullptr, p_oa, MQ, NOA, CC);

    // 4. softmax + bilinear sample + head-reduce
    sample_kernel<<<MQ, 192>>>(refp, p_attn);

    // 5. output projection + residual -> q2   (24576 x 768 x 768)
    gemm_tf32_kernel<<<dim3(CC/128, MQ/128), 256, GEMM_SMEM>>>(p_attn, op_w, op_b, query, p_q2, MQ, CC, CC);

    // 6. ConvFFN
    ln_kernel<<<MQ, 192>>>(p_q2, ffn_w, ffn_b, p_qln);
    gemm_tf32_kernel<<<dim3((HID+127)/128, MQ/128), 256, GEMM_SMEM>>>(p_qln, fc1_w, fc1_b, nullptr, p_x1, MQ, HID, CC);
    dwconv_gelu_kernel<<<MQ, HID>>>(p_x1, dw_w, dw_b, p_x2);
    gemm_tf32_kernel<<<dim3(CC/128, MQ/128), 256, GEMM_SMEM>>>(p_x2, fc2_w, fc2_b, p_q2, out, MQ, CC, HID);
}